// round 1
// baseline (speedup 1.0000x reference)
#include <cuda_runtime.h>

#define T_LEN   4096
#define NBATCH  16
#define BT      (NBATCH * T_LEN)   // 65536 tokens
#define CDIM    256
#define HID     1024
#define OUTC    128
#define NLAYER  20
#define RMS_EPS 1e-6f

// ---------------- scratch (static __device__, no allocs) ----------------
__device__ float g_z[BT * CDIM];     // residual stream (token-major: [m][c])
__device__ float g_zn[BT * CDIM];    // normed activations / head "on"
__device__ float g_u[BT * CDIM];     // gated conv output
__device__ float g_sum[BT * CDIM];   // skip accumulator
__device__ float g_h[BT * HID];      // head hidden

// ---------------- packed f32x2 helpers ----------------
typedef unsigned long long u64;

__device__ __forceinline__ u64 dup2(float x) {
    u64 r;
    asm("mov.b64 %0, {%1, %1};" : "=l"(r) : "r"(__float_as_uint(x)));
    return r;
}
__device__ __forceinline__ void ffma2(u64& acc, u64 a, u64 b) {
    asm("fma.rn.f32x2 %0, %1, %2, %0;" : "+l"(acc) : "l"(a), "l"(b));
}
__device__ __forceinline__ float2 unpk(u64 v) {
    unsigned lo, hi;
    asm("mov.b64 {%0, %1}, %2;" : "=r"(lo), "=r"(hi) : "l"(v));
    float2 r;
    r.x = __uint_as_float(lo);
    r.y = __uint_as_float(hi);
    return r;
}

// ---------------- zero kernel (skip accumulator init) ----------------
__global__ void k_zero(float* __restrict__ p) {
    p[blockIdx.x * 256 + threadIdx.x] = 0.f;
}

// ---------------- RMS norm (optionally relu input first) ----------------
// one warp per token; 8 contiguous floats per lane (coalesced float4 pairs)
template <bool RELU_IN>
__global__ void k_norm(const float* __restrict__ z, const float* __restrict__ w,
                       float* __restrict__ o) {
    int m = blockIdx.x * 8 + threadIdx.y;
    int lane = threadIdx.x;
    const float* row = z + m * CDIM;
    float4 v0 = *(const float4*)&row[lane * 8];
    float4 v1 = *(const float4*)&row[lane * 8 + 4];
    if (RELU_IN) {
        v0.x = fmaxf(v0.x, 0.f); v0.y = fmaxf(v0.y, 0.f);
        v0.z = fmaxf(v0.z, 0.f); v0.w = fmaxf(v0.w, 0.f);
        v1.x = fmaxf(v1.x, 0.f); v1.y = fmaxf(v1.y, 0.f);
        v1.z = fmaxf(v1.z, 0.f); v1.w = fmaxf(v1.w, 0.f);
    }
    float s = v0.x * v0.x + v0.y * v0.y + v0.z * v0.z + v0.w * v0.w
            + v1.x * v1.x + v1.y * v1.y + v1.z * v1.z + v1.w * v1.w;
#pragma unroll
    for (int off = 16; off; off >>= 1) s += __shfl_xor_sync(0xffffffffu, s, off);
    float inv = rsqrtf(s * (1.f / CDIM) + RMS_EPS);
    float4 w0 = *(const float4*)&w[lane * 8];
    float4 w1 = *(const float4*)&w[lane * 8 + 4];
    float* orow = o + m * CDIM;
    float4 r0 = make_float4(v0.x * inv * w0.x, v0.y * inv * w0.y,
                            v0.z * inv * w0.z, v0.w * inv * w0.w);
    float4 r1 = make_float4(v1.x * inv * w1.x, v1.y * inv * w1.y,
                            v1.z * inv * w1.z, v1.w * inv * w1.w);
    *(float4*)&orow[lane * 8] = r0;
    *(float4*)&orow[lane * 8 + 4] = r1;
}

// ---------------- input conv: GEMM with im2col gather ----------------
// A[m][kk], kk = ci*32 + k, value = x[(m-31+k)*8 + ci] (causal zero-pad)
// W_in row-major (256, 256): W[co*256 + ci*32 + k]
__global__ __launch_bounds__(256) void k_inconv(
    const float* __restrict__ x, const float* __restrict__ W,
    const float* __restrict__ bias, float* __restrict__ out) {
    __shared__ __align__(16) float As[16][68];
    __shared__ __align__(16) float Ws[16][68];
    int tid = threadIdx.x;
    int tx = tid & 15, ty = tid >> 4;
    int m0 = blockIdx.y * 64, n0 = blockIdx.x * 64;
    u64 acc[4][2] = {};
    int ml = tid >> 2;
    int k4 = (tid & 3) << 2;
    int m = m0 + ml;
    int t = m & (T_LEN - 1);
    for (int kt = 0; kt < 256; kt += 16) {
#pragma unroll
        for (int j = 0; j < 4; j++) {
            int kk = kt + k4 + j;
            int ci = kk >> 5, k = kk & 31;
            float v = 0.f;
            if (t + k >= 31) v = x[(m - 31 + k) * 8 + ci];
            As[k4 + j][ml] = v;
        }
        float4 w4 = *(const float4*)&W[(n0 + ml) * 256 + kt + k4];
        Ws[k4 + 0][ml] = w4.x; Ws[k4 + 1][ml] = w4.y;
        Ws[k4 + 2][ml] = w4.z; Ws[k4 + 3][ml] = w4.w;
        __syncthreads();
#pragma unroll
        for (int kk = 0; kk < 16; kk++) {
            float a[4];
            *(float4*)a = *(const float4*)&As[kk][ty * 4];
            ulonglong2 wv = *(const ulonglong2*)&Ws[kk][tx * 4];
#pragma unroll
            for (int i = 0; i < 4; i++) {
                u64 ai = dup2(a[i]);
                ffma2(acc[i][0], ai, wv.x);
                ffma2(acc[i][1], ai, wv.y);
            }
        }
        __syncthreads();
    }
#pragma unroll
    for (int i = 0; i < 4; i++) {
        int mi = m0 + ty * 4 + i;
#pragma unroll
        for (int p = 0; p < 2; p++) {
            int n_ = n0 + tx * 4 + p * 2;
            float2 c = unpk(acc[i][p]);
            out[mi * CDIM + n_]     = c.x + bias[n_];
            out[mi * CDIM + n_ + 1] = c.y + bias[n_ + 1];
        }
    }
}

// ---------------- fused f/g dilated conv + gate ----------------
// u[m][co] = tanh(f) * sigmoid(g),
// f = sum_ci Wf[co][ci][0]*zn[m-d][ci] + Wf[co][ci][1]*zn[m][ci]  (+bf)
// K = 512: kk<256 -> tap0 (t-d), kk>=256 -> tap1 (t)
__global__ __launch_bounds__(256) void k_fg(
    const float* __restrict__ zn, const float* __restrict__ Wf,
    const float* __restrict__ Wg, const float* __restrict__ bf,
    const float* __restrict__ bg, float* __restrict__ u, int d) {
    __shared__ __align__(16) float As[16][68];
    __shared__ __align__(16) float Wsf[16][68];
    __shared__ __align__(16) float Wsg[16][68];
    int tid = threadIdx.x;
    int tx = tid & 15, ty = tid >> 4;
    int m0 = blockIdx.y * 64, n0 = blockIdx.x * 64;
    u64 accf[4][2] = {}, accg[4][2] = {};
    int ml = tid >> 2;
    int k4 = (tid & 3) << 2;
    int m = m0 + ml;
    int t = m & (T_LEN - 1);
    for (int kt = 0; kt < 512; kt += 16) {
        int tap = kt >> 8;                 // 0: uses zn[t-d], 1: uses zn[t]
        int ci0 = (kt & 255) + k4;
        float4 av;
        if (tap) {
            av = *(const float4*)&zn[m * CDIM + ci0];
        } else if (t >= d) {
            av = *(const float4*)&zn[(m - d) * CDIM + ci0];
        } else {
            av = make_float4(0.f, 0.f, 0.f, 0.f);
        }
        As[k4 + 0][ml] = av.x; As[k4 + 1][ml] = av.y;
        As[k4 + 2][ml] = av.z; As[k4 + 3][ml] = av.w;
        const float* wf = Wf + (n0 + ml) * 512 + ci0 * 2 + tap;
        const float* wg = Wg + (n0 + ml) * 512 + ci0 * 2 + tap;
#pragma unroll
        for (int j = 0; j < 4; j++) {
            Wsf[k4 + j][ml] = wf[2 * j];
            Wsg[k4 + j][ml] = wg[2 * j];
        }
        __syncthreads();
#pragma unroll
        for (int kk = 0; kk < 16; kk++) {
            float a[4];
            *(float4*)a = *(const float4*)&As[kk][ty * 4];
            ulonglong2 wfv = *(const ulonglong2*)&Wsf[kk][tx * 4];
            ulonglong2 wgv = *(const ulonglong2*)&Wsg[kk][tx * 4];
#pragma unroll
            for (int i = 0; i < 4; i++) {
                u64 ai = dup2(a[i]);
                ffma2(accf[i][0], ai, wfv.x);
                ffma2(accf[i][1], ai, wfv.y);
                ffma2(accg[i][0], ai, wgv.x);
                ffma2(accg[i][1], ai, wgv.y);
            }
        }
        __syncthreads();
    }
#pragma unroll
    for (int i = 0; i < 4; i++) {
        int mi = m0 + ty * 4 + i;
#pragma unroll
        for (int p = 0; p < 2; p++) {
            int n_ = n0 + tx * 4 + p * 2;
            float2 f2 = unpk(accf[i][p]);
            float2 g2 = unpk(accg[i][p]);
            float f0 = tanhf(f2.x + bf[n_]);
            float f1 = tanhf(f2.y + bf[n_ + 1]);
            float g0 = 1.f / (1.f + expf(-(g2.x + bg[n_])));
            float g1 = 1.f / (1.f + expf(-(g2.y + bg[n_ + 1])));
            u[mi * CDIM + n_]     = f0 * g0;
            u[mi * CDIM + n_ + 1] = f1 * g1;
        }
    }
}

// ---------------- fused residual + skip 1x1 convs ----------------
// z[m][co] += u @ Wr^T + br ;  sum[m][co] += u @ Ws^T + bs
__global__ __launch_bounds__(256) void k_rs(
    const float* __restrict__ u, const float* __restrict__ Wr,
    const float* __restrict__ Wsc, const float* __restrict__ br,
    const float* __restrict__ bs, float* __restrict__ z,
    float* __restrict__ sacc) {
    __shared__ __align__(16) float As[16][68];
    __shared__ __align__(16) float Wsr[16][68];
    __shared__ __align__(16) float Wss[16][68];
    int tid = threadIdx.x;
    int tx = tid & 15, ty = tid >> 4;
    int m0 = blockIdx.y * 64, n0 = blockIdx.x * 64;
    u64 accr[4][2] = {}, accs[4][2] = {};
    int ml = tid >> 2;
    int k4 = (tid & 3) << 2;
    int m = m0 + ml;
    for (int kt = 0; kt < 256; kt += 16) {
        float4 av = *(const float4*)&u[m * CDIM + kt + k4];
        As[k4 + 0][ml] = av.x; As[k4 + 1][ml] = av.y;
        As[k4 + 2][ml] = av.z; As[k4 + 3][ml] = av.w;
        float4 wr4 = *(const float4*)&Wr[(n0 + ml) * CDIM + kt + k4];
        float4 ws4 = *(const float4*)&Wsc[(n0 + ml) * CDIM + kt + k4];
        Wsr[k4 + 0][ml] = wr4.x; Wsr[k4 + 1][ml] = wr4.y;
        Wsr[k4 + 2][ml] = wr4.z; Wsr[k4 + 3][ml] = wr4.w;
        Wss[k4 + 0][ml] = ws4.x; Wss[k4 + 1][ml] = ws4.y;
        Wss[k4 + 2][ml] = ws4.z; Wss[k4 + 3][ml] = ws4.w;
        __syncthreads();
#pragma unroll
        for (int kk = 0; kk < 16; kk++) {
            float a[4];
            *(float4*)a = *(const float4*)&As[kk][ty * 4];
            ulonglong2 wrv = *(const ulonglong2*)&Wsr[kk][tx * 4];
            ulonglong2 wsv = *(const ulonglong2*)&Wss[kk][tx * 4];
#pragma unroll
            for (int i = 0; i < 4; i++) {
                u64 ai = dup2(a[i]);
                ffma2(accr[i][0], ai, wrv.x);
                ffma2(accr[i][1], ai, wrv.y);
                ffma2(accs[i][0], ai, wsv.x);
                ffma2(accs[i][1], ai, wsv.y);
            }
        }
        __syncthreads();
    }
#pragma unroll
    for (int i = 0; i < 4; i++) {
        int mi = m0 + ty * 4 + i;
#pragma unroll
        for (int p = 0; p < 2; p++) {
            int n_ = n0 + tx * 4 + p * 2;
            float2 r2 = unpk(accr[i][p]);
            float2 s2 = unpk(accs[i][p]);
            z[mi * CDIM + n_]        += r2.x + br[n_];
            z[mi * CDIM + n_ + 1]    += r2.y + br[n_ + 1];
            sacc[mi * CDIM + n_]     += s2.x + bs[n_];
            sacc[mi * CDIM + n_ + 1] += s2.y + bs[n_ + 1];
        }
    }
}

// ---------------- generic GEMM: C = act(A @ W^T + bias) ----------------
// A: M x K row-major, W: N x K row-major, C: M x N
template <int K, bool RELU>
__global__ __launch_bounds__(256) void k_gemm(
    const float* __restrict__ A, const float* __restrict__ W,
    const float* __restrict__ bias, float* __restrict__ C, int N) {
    __shared__ __align__(16) float As[16][68];
    __shared__ __align__(16) float Ws[16][68];
    int tid = threadIdx.x;
    int tx = tid & 15, ty = tid >> 4;
    int m0 = blockIdx.y * 64, n0 = blockIdx.x * 64;
    u64 acc[4][2] = {};
    int ml = tid >> 2;
    int k4 = (tid & 3) << 2;
    int m = m0 + ml;
    for (int kt = 0; kt < K; kt += 16) {
        float4 av = *(const float4*)&A[m * K + kt + k4];
        As[k4 + 0][ml] = av.x; As[k4 + 1][ml] = av.y;
        As[k4 + 2][ml] = av.z; As[k4 + 3][ml] = av.w;
        float4 w4 = *(const float4*)&W[(n0 + ml) * K + kt + k4];
        Ws[k4 + 0][ml] = w4.x; Ws[k4 + 1][ml] = w4.y;
        Ws[k4 + 2][ml] = w4.z; Ws[k4 + 3][ml] = w4.w;
        __syncthreads();
#pragma unroll
        for (int kk = 0; kk < 16; kk++) {
            float a[4];
            *(float4*)a = *(const float4*)&As[kk][ty * 4];
            ulonglong2 wv = *(const ulonglong2*)&Ws[kk][tx * 4];
#pragma unroll
            for (int i = 0; i < 4; i++) {
                u64 ai = dup2(a[i]);
                ffma2(acc[i][0], ai, wv.x);
                ffma2(acc[i][1], ai, wv.y);
            }
        }
        __syncthreads();
    }
#pragma unroll
    for (int i = 0; i < 4; i++) {
        int mi = m0 + ty * 4 + i;
#pragma unroll
        for (int p = 0; p < 2; p++) {
            int n_ = n0 + tx * 4 + p * 2;
            float2 c = unpk(acc[i][p]);
            float v0 = c.x + bias[n_];
            float v1 = c.y + bias[n_ + 1];
            if (RELU) { v0 = fmaxf(v0, 0.f); v1 = fmaxf(v1, 0.f); }
            C[mi * N + n_]     = v0;
            C[mi * N + n_ + 1] = v1;
        }
    }
}

// ---------------- launch ----------------
extern "C" void kernel_launch(void* const* d_in, const int* in_sizes, int n_in,
                              void* d_out, int out_size) {
    const float* x           = (const float*)d_in[0];
    const float* W_in        = (const float*)d_in[1];
    const float* b_in        = (const float*)d_in[2];
    const float* W_f         = (const float*)d_in[3];
    const float* b_f         = (const float*)d_in[4];
    const float* W_g         = (const float*)d_in[5];
    const float* b_g         = (const float*)d_in[6];
    const float* W_r         = (const float*)d_in[7];
    const float* b_r         = (const float*)d_in[8];
    const float* W_s         = (const float*)d_in[9];
    const float* b_s         = (const float*)d_in[10];
    const float* norm_w      = (const float*)d_in[11];
    const float* head_norm_w = (const float*)d_in[12];
    const float* W1          = (const float*)d_in[13];
    const float* b1          = (const float*)d_in[14];
    const float* W2          = (const float*)d_in[15];
    const float* b2          = (const float*)d_in[16];
    float* out = (float*)d_out;

    float *zp, *znp, *up, *sump, *hp;
    cudaGetSymbolAddress((void**)&zp, g_z);
    cudaGetSymbolAddress((void**)&znp, g_zn);
    cudaGetSymbolAddress((void**)&up, g_u);
    cudaGetSymbolAddress((void**)&sump, g_sum);
    cudaGetSymbolAddress((void**)&hp, g_h);

    static const int DIL[NLAYER] = {1, 2, 4, 8, 16, 32, 64, 128, 256, 512,
                                    1, 2, 4, 8, 16, 32, 64, 128, 256, 512};

    dim3 gC(CDIM / 64, BT / 64);      // (4, 1024)
    dim3 nrmB(32, 8);

    k_zero<<<BT * CDIM / 256, 256>>>(sump);
    k_inconv<<<gC, 256>>>(x, W_in, b_in, zp);

    for (int i = 0; i < NLAYER; i++) {
        k_norm<false><<<BT / 8, nrmB>>>(zp, norm_w + i * CDIM, znp);
        k_fg<<<gC, 256>>>(znp,
                          W_f + (size_t)i * CDIM * CDIM * 2,
                          W_g + (size_t)i * CDIM * CDIM * 2,
                          b_f + i * CDIM, b_g + i * CDIM, up, DIL[i]);
        k_rs<<<gC, 256>>>(up,
                          W_r + (size_t)i * CDIM * CDIM,
                          W_s + (size_t)i * CDIM * CDIM,
                          b_r + i * CDIM, b_s + i * CDIM, zp, sump);
    }

    k_norm<true><<<BT / 8, nrmB>>>(sump, head_norm_w, znp);
    k_gemm<CDIM, true><<<dim3(HID / 64, BT / 64), 256>>>(znp, W1, b1, hp, HID);
    k_gemm<HID, false><<<dim3(OUTC / 64, BT / 64), 256>>>(hp, W2, b2, out, OUTC);
}

// round 2
// speedup vs baseline: 3.5897x; 3.5897x over previous
#include <cuda_runtime.h>

#define T_LEN   4096
#define NBATCH  16
#define BT      (NBATCH * T_LEN)   // 65536 tokens
#define CDIM    256
#define HID     1024
#define OUTC    128
#define NLAYER  20
#define RMS_EPS 1e-6f
#define KC      32                 // K chunk
#define ASTR    36                 // smem row stride in floats (conflict-free)

// ---------------- scratch (static __device__, no allocs) ----------------
__device__ float g_z[BT * CDIM];     // residual stream fp32
__device__ float g_zn[BT * CDIM];    // normed activations (tf32-rounded)
__device__ float g_u[BT * CDIM];     // gated conv output (tf32-rounded)
__device__ float g_sum[BT * CDIM];   // skip accumulator fp32
__device__ float g_h[BT * HID];      // head hidden (tf32-rounded)
// pre-rounded / repacked weights
__device__ float g_Wfp[NLAYER * 2 * CDIM * CDIM];  // [l][tap][co][ci]
__device__ float g_Wgp[NLAYER * 2 * CDIM * CDIM];
__device__ float g_Wrp[NLAYER * CDIM * CDIM];
__device__ float g_Wsp[NLAYER * CDIM * CDIM];
__device__ float g_W1p[HID * CDIM];
__device__ float g_W2p[OUTC * HID];

// ---------------- helpers ----------------
typedef unsigned long long u64;

__device__ __forceinline__ float rndf(float f) {   // round to nearest tf32
    unsigned r;
    asm("cvt.rna.tf32.f32 %0, %1;" : "=r"(r) : "f"(f));
    return __uint_as_float(r);
}
__device__ __forceinline__ float sigm(float x) {
    return 1.f / (1.f + __expf(-x));
}

#define MMA_TF32(d, a, b0, b1)                                              \
    asm volatile("mma.sync.aligned.m16n8k8.row.col.f32.tf32.tf32.f32 "      \
                 "{%0,%1,%2,%3}, {%4,%5,%6,%7}, {%8,%9}, {%0,%1,%2,%3};"    \
                 : "+f"(d[0]), "+f"(d[1]), "+f"(d[2]), "+f"(d[3])           \
                 : "r"(a[0]), "r"(a[1]), "r"(a[2]), "r"(a[3]),              \
                   "r"(b0), "r"(b1))

#define CP16(s, g)                                                          \
    asm volatile("cp.async.cg.shared.global [%0], [%1], 16;" :: "r"(s), "l"(g))
#define CP16Z(s, g)                                                         \
    asm volatile("cp.async.cg.shared.global [%0], [%1], 16, 0;" :: "r"(s), "l"(g))
#define CP_COMMIT() asm volatile("cp.async.commit_group;" ::: "memory")
#define CP_WAIT1()  asm volatile("cp.async.wait_group 1;" ::: "memory")
#define CP_WAIT0()  asm volatile("cp.async.wait_group 0;" ::: "memory")

// packed f32x2 helpers (for inconv, kept from R1)
__device__ __forceinline__ u64 dup2(float x) {
    u64 r;
    asm("mov.b64 %0, {%1, %1};" : "=l"(r) : "r"(__float_as_uint(x)));
    return r;
}
__device__ __forceinline__ void ffma2(u64& acc, u64 a, u64 b) {
    asm("fma.rn.f32x2 %0, %1, %2, %0;" : "+l"(acc) : "l"(a), "l"(b));
}
__device__ __forceinline__ float2 unpk(u64 v) {
    unsigned lo, hi;
    asm("mov.b64 {%0, %1}, %2;" : "=r"(lo), "=r"(hi) : "l"(v));
    float2 r;
    r.x = __uint_as_float(lo);
    r.y = __uint_as_float(hi);
    return r;
}

// ---------------- weight prep ----------------
// fg: out[l][tap][co][ci] = rnd(in[l][co][ci*2+tap])
__global__ void k_prep_fg(const float* __restrict__ Wf, const float* __restrict__ Wg,
                          float* __restrict__ Wfp, float* __restrict__ Wgp) {
    int i = blockIdx.x * 256 + threadIdx.x;
    int ci = i & 255;
    int co = (i >> 8) & 255;
    int tap = (i >> 16) & 1;
    int l = i >> 17;
    int src = (l << 17) + (co << 9) + ci * 2 + tap;
    Wfp[i] = rndf(Wf[src]);
    Wgp[i] = rndf(Wg[src]);
}
__global__ void k_prep_round(const float* __restrict__ in, float* __restrict__ out, int n) {
    int i = blockIdx.x * 256 + threadIdx.x;
    if (i < n) out[i] = rndf(in[i]);
}
__global__ void k_zero(float* __restrict__ p) {
    p[blockIdx.x * 256 + threadIdx.x] = 0.f;
}

// ---------------- RMS norm (outputs tf32-rounded) ----------------
template <bool RELU_IN>
__global__ void k_norm(const float* __restrict__ z, const float* __restrict__ w,
                       float* __restrict__ o) {
    int m = blockIdx.x * 8 + threadIdx.y;
    int lane = threadIdx.x;
    const float* row = z + (size_t)m * CDIM;
    float4 v0 = *(const float4*)&row[lane * 8];
    float4 v1 = *(const float4*)&row[lane * 8 + 4];
    if (RELU_IN) {
        v0.x = fmaxf(v0.x, 0.f); v0.y = fmaxf(v0.y, 0.f);
        v0.z = fmaxf(v0.z, 0.f); v0.w = fmaxf(v0.w, 0.f);
        v1.x = fmaxf(v1.x, 0.f); v1.y = fmaxf(v1.y, 0.f);
        v1.z = fmaxf(v1.z, 0.f); v1.w = fmaxf(v1.w, 0.f);
    }
    float s = v0.x * v0.x + v0.y * v0.y + v0.z * v0.z + v0.w * v0.w
            + v1.x * v1.x + v1.y * v1.y + v1.z * v1.z + v1.w * v1.w;
#pragma unroll
    for (int off = 16; off; off >>= 1) s += __shfl_xor_sync(0xffffffffu, s, off);
    float inv = rsqrtf(s * (1.f / CDIM) + RMS_EPS);
    float4 w0 = *(const float4*)&w[lane * 8];
    float4 w1 = *(const float4*)&w[lane * 8 + 4];
    float* orow = o + (size_t)m * CDIM;
    float4 r0 = make_float4(rndf(v0.x * inv * w0.x), rndf(v0.y * inv * w0.y),
                            rndf(v0.z * inv * w0.z), rndf(v0.w * inv * w0.w));
    float4 r1 = make_float4(rndf(v1.x * inv * w1.x), rndf(v1.y * inv * w1.y),
                            rndf(v1.z * inv * w1.z), rndf(v1.w * inv * w1.w));
    *(float4*)&orow[lane * 8] = r0;
    *(float4*)&orow[lane * 8 + 4] = r1;
}

// ---------------- input conv (FFMA2, unchanged; writes fp32 z) ----------------
__global__ __launch_bounds__(256) void k_inconv(
    const float* __restrict__ x, const float* __restrict__ W,
    const float* __restrict__ bias, float* __restrict__ out) {
    __shared__ __align__(16) float As[16][68];
    __shared__ __align__(16) float Ws[16][68];
    int tid = threadIdx.x;
    int tx = tid & 15, ty = tid >> 4;
    int m0 = blockIdx.y * 64, n0 = blockIdx.x * 64;
    u64 acc[4][2] = {};
    int ml = tid >> 2;
    int k4 = (tid & 3) << 2;
    int m = m0 + ml;
    int t = m & (T_LEN - 1);
    for (int kt = 0; kt < 256; kt += 16) {
#pragma unroll
        for (int j = 0; j < 4; j++) {
            int kk = kt + k4 + j;
            int ci = kk >> 5, k = kk & 31;
            float v = 0.f;
            if (t + k >= 31) v = x[(m - 31 + k) * 8 + ci];
            As[k4 + j][ml] = v;
        }
        float4 w4 = *(const float4*)&W[(n0 + ml) * 256 + kt + k4];
        Ws[k4 + 0][ml] = w4.x; Ws[k4 + 1][ml] = w4.y;
        Ws[k4 + 2][ml] = w4.z; Ws[k4 + 3][ml] = w4.w;
        __syncthreads();
#pragma unroll
        for (int kk = 0; kk < 16; kk++) {
            float a[4];
            *(float4*)a = *(const float4*)&As[kk][ty * 4];
            ulonglong2 wv = *(const ulonglong2*)&Ws[kk][tx * 4];
#pragma unroll
            for (int i = 0; i < 4; i++) {
                u64 ai = dup2(a[i]);
                ffma2(acc[i][0], ai, wv.x);
                ffma2(acc[i][1], ai, wv.y);
            }
        }
        __syncthreads();
    }
#pragma unroll
    for (int i = 0; i < 4; i++) {
        int mi = m0 + ty * 4 + i;
#pragma unroll
        for (int p = 0; p < 2; p++) {
            int n_ = n0 + tx * 4 + p * 2;
            float2 c = unpk(acc[i][p]);
            out[mi * CDIM + n_]     = c.x + bias[n_];
            out[mi * CDIM + n_ + 1] = c.y + bias[n_ + 1];
        }
    }
}

// =====================================================================
// tf32 tensor-core GEMM kernels: CTA tile 128(M) x 64(N), K-chunk 32,
// 8 warps (4m x 2n), warp tile 32x32, m16n8k8 mma, cp.async 2-stage.
// =====================================================================

// ---- fused f/g dilated conv + gate: u = tanh(f)*sigmoid(g) ----
// Wf/Wg packed [tap][co][ci], chunks 0-7 = tap0 (zn[t-d]), 8-15 = tap1 (zn[t])
__global__ __launch_bounds__(256, 2) void k_fg(
    const float* __restrict__ zn, const float* __restrict__ Wf,
    const float* __restrict__ Wg, const float* __restrict__ bf,
    const float* __restrict__ bg, float* __restrict__ u, int d) {
    extern __shared__ float sm[];
    const int STG = 128 * ASTR + 2 * 64 * ASTR;   // 9216 floats
    int tid = threadIdx.x;
    int lane = tid & 31, wid = tid >> 5;
    int wm = (wid & 3) * 32, wn = (wid >> 2) * 32;
    int m0 = blockIdx.y * 128, n0 = blockIdx.x * 64;

    float af[2][4][4] = {}, ag[2][4][4] = {};

    auto issue = [&](int chunk, int st) {
        int tap = chunk >= 8;
        int ci0 = (chunk & 7) * KC;
        float* As = sm + st * STG;
        float* Fs = As + 128 * ASTR;
        float* Gs = Fs + 64 * ASTR;
#pragma unroll
        for (int j = 0; j < 4; j++) {
            int idx = tid + 256 * j;
            int row = idx >> 3, cg = idx & 7;
            int m = m0 + row;
            int t = m & (T_LEN - 1);
            unsigned sa = (unsigned)__cvta_generic_to_shared(As + row * ASTR + cg * 4);
            if (tap) {
                CP16(sa, zn + (size_t)m * CDIM + ci0 + cg * 4);
            } else if (t >= d) {
                CP16(sa, zn + (size_t)(m - d) * CDIM + ci0 + cg * 4);
            } else {
                CP16Z(sa, zn);
            }
        }
        const float* Wfc = Wf + (size_t)tap * CDIM * CDIM;
        const float* Wgc = Wg + (size_t)tap * CDIM * CDIM;
#pragma unroll
        for (int j = 0; j < 2; j++) {
            int idx = tid + 256 * j;
            int row = idx >> 3, cg = idx & 7;
            unsigned sf = (unsigned)__cvta_generic_to_shared(Fs + row * ASTR + cg * 4);
            unsigned sg = (unsigned)__cvta_generic_to_shared(Gs + row * ASTR + cg * 4);
            CP16(sf, Wfc + (size_t)(n0 + row) * CDIM + ci0 + cg * 4);
            CP16(sg, Wgc + (size_t)(n0 + row) * CDIM + ci0 + cg * 4);
        }
    };

    int r = lane >> 2, c = lane & 3;

    issue(0, 0);
    CP_COMMIT();
    for (int chunk = 0; chunk < 16; chunk++) {
        int st = chunk & 1;
        if (chunk + 1 < 16) {
            issue(chunk + 1, st ^ 1);
            CP_COMMIT();
            CP_WAIT1();
        } else {
            CP_WAIT0();
        }
        __syncthreads();
        const float* As = sm + st * STG;
        const float* Fs = As + 128 * ASTR;
        const float* Gs = Fs + 64 * ASTR;
#pragma unroll
        for (int k8 = 0; k8 < 4; k8++) {
            int kb = k8 * 8;
            unsigned a[2][4];
#pragma unroll
            for (int mt = 0; mt < 2; mt++) {
                const float* ab = As + (wm + mt * 16 + r) * ASTR + kb + c;
                a[mt][0] = __float_as_uint(ab[0]);
                a[mt][1] = __float_as_uint(ab[8 * ASTR]);
                a[mt][2] = __float_as_uint(ab[4]);
                a[mt][3] = __float_as_uint(ab[8 * ASTR + 4]);
            }
#pragma unroll
            for (int nt = 0; nt < 4; nt++) {
                const float* fb = Fs + (wn + nt * 8 + r) * ASTR + kb + c;
                unsigned b0 = __float_as_uint(fb[0]);
                unsigned b1 = __float_as_uint(fb[4]);
                MMA_TF32(af[0][nt], a[0], b0, b1);
                MMA_TF32(af[1][nt], a[1], b0, b1);
                const float* gb = Gs + (wn + nt * 8 + r) * ASTR + kb + c;
                unsigned g0 = __float_as_uint(gb[0]);
                unsigned g1 = __float_as_uint(gb[4]);
                MMA_TF32(ag[0][nt], a[0], g0, g1);
                MMA_TF32(ag[1][nt], a[1], g0, g1);
            }
        }
        __syncthreads();
    }

    int c2 = (lane & 3) * 2;
#pragma unroll
    for (int mt = 0; mt < 2; mt++) {
        int mrow = m0 + wm + mt * 16 + r;
#pragma unroll
        for (int nt = 0; nt < 4; nt++) {
            int col = n0 + wn + nt * 8 + c2;
            float2 bfv = *(const float2*)&bf[col];
            float2 bgv = *(const float2*)&bg[col];
            float v0 = rndf(tanhf(af[mt][nt][0] + bfv.x) * sigm(ag[mt][nt][0] + bgv.x));
            float v1 = rndf(tanhf(af[mt][nt][1] + bfv.y) * sigm(ag[mt][nt][1] + bgv.y));
            float v2 = rndf(tanhf(af[mt][nt][2] + bfv.x) * sigm(ag[mt][nt][2] + bgv.x));
            float v3 = rndf(tanhf(af[mt][nt][3] + bfv.y) * sigm(ag[mt][nt][3] + bgv.y));
            *(float2*)&u[(size_t)mrow * CDIM + col] = make_float2(v0, v1);
            *(float2*)&u[(size_t)(mrow + 8) * CDIM + col] = make_float2(v2, v3);
        }
    }
}

// ---- fused residual + skip 1x1 convs: z += u@Wr^T+br ; sum += u@Ws^T+bs ----
__global__ __launch_bounds__(256, 2) void k_rs(
    const float* __restrict__ u, const float* __restrict__ Wr,
    const float* __restrict__ Ws, const float* __restrict__ br,
    const float* __restrict__ bs, float* __restrict__ z,
    float* __restrict__ sacc) {
    extern __shared__ float sm[];
    const int STG = 128 * ASTR + 2 * 64 * ASTR;
    int tid = threadIdx.x;
    int lane = tid & 31, wid = tid >> 5;
    int wm = (wid & 3) * 32, wn = (wid >> 2) * 32;
    int m0 = blockIdx.y * 128, n0 = blockIdx.x * 64;

    float ar[2][4][4] = {}, as_[2][4][4] = {};

    auto issue = [&](int chunk, int st) {
        int ci0 = chunk * KC;
        float* As = sm + st * STG;
        float* Rs = As + 128 * ASTR;
        float* Ss = Rs + 64 * ASTR;
#pragma unroll
        for (int j = 0; j < 4; j++) {
            int idx = tid + 256 * j;
            int row = idx >> 3, cg = idx & 7;
            unsigned sa = (unsigned)__cvta_generic_to_shared(As + row * ASTR + cg * 4);
            CP16(sa, u + (size_t)(m0 + row) * CDIM + ci0 + cg * 4);
        }
#pragma unroll
        for (int j = 0; j < 2; j++) {
            int idx = tid + 256 * j;
            int row = idx >> 3, cg = idx & 7;
            unsigned sr = (unsigned)__cvta_generic_to_shared(Rs + row * ASTR + cg * 4);
            unsigned ss = (unsigned)__cvta_generic_to_shared(Ss + row * ASTR + cg * 4);
            CP16(sr, Wr + (size_t)(n0 + row) * CDIM + ci0 + cg * 4);
            CP16(ss, Ws + (size_t)(n0 + row) * CDIM + ci0 + cg * 4);
        }
    };

    int r = lane >> 2, c = lane & 3;

    issue(0, 0);
    CP_COMMIT();
    for (int chunk = 0; chunk < 8; chunk++) {
        int st = chunk & 1;
        if (chunk + 1 < 8) {
            issue(chunk + 1, st ^ 1);
            CP_COMMIT();
            CP_WAIT1();
        } else {
            CP_WAIT0();
        }
        __syncthreads();
        const float* As = sm + st * STG;
        const float* Rs = As + 128 * ASTR;
        const float* Ss = Rs + 64 * ASTR;
#pragma unroll
        for (int k8 = 0; k8 < 4; k8++) {
            int kb = k8 * 8;
            unsigned a[2][4];
#pragma unroll
            for (int mt = 0; mt < 2; mt++) {
                const float* ab = As + (wm + mt * 16 + r) * ASTR + kb + c;
                a[mt][0] = __float_as_uint(ab[0]);
                a[mt][1] = __float_as_uint(ab[8 * ASTR]);
                a[mt][2] = __float_as_uint(ab[4]);
                a[mt][3] = __float_as_uint(ab[8 * ASTR + 4]);
            }
#pragma unroll
            for (int nt = 0; nt < 4; nt++) {
                const float* rb = Rs + (wn + nt * 8 + r) * ASTR + kb + c;
                unsigned b0 = __float_as_uint(rb[0]);
                unsigned b1 = __float_as_uint(rb[4]);
                MMA_TF32(ar[0][nt], a[0], b0, b1);
                MMA_TF32(ar[1][nt], a[1], b0, b1);
                const float* sb = Ss + (wn + nt * 8 + r) * ASTR + kb + c;
                unsigned s0 = __float_as_uint(sb[0]);
                unsigned s1 = __float_as_uint(sb[4]);
                MMA_TF32(as_[0][nt], a[0], s0, s1);
                MMA_TF32(as_[1][nt], a[1], s0, s1);
            }
        }
        __syncthreads();
    }

    int c2 = (lane & 3) * 2;
#pragma unroll
    for (int mt = 0; mt < 2; mt++) {
        int mrow = m0 + wm + mt * 16 + r;
#pragma unroll
        for (int nt = 0; nt < 4; nt++) {
            int col = n0 + wn + nt * 8 + c2;
            float2 brv = *(const float2*)&br[col];
            float2 bsv = *(const float2*)&bs[col];
            size_t i0 = (size_t)mrow * CDIM + col;
            size_t i1 = (size_t)(mrow + 8) * CDIM + col;
            float2 z0 = *(float2*)&z[i0];
            float2 z1 = *(float2*)&z[i1];
            z0.x += ar[mt][nt][0] + brv.x; z0.y += ar[mt][nt][1] + brv.y;
            z1.x += ar[mt][nt][2] + brv.x; z1.y += ar[mt][nt][3] + brv.y;
            *(float2*)&z[i0] = z0;
            *(float2*)&z[i1] = z1;
            float2 s0 = *(float2*)&sacc[i0];
            float2 s1 = *(float2*)&sacc[i1];
            s0.x += as_[mt][nt][0] + bsv.x; s0.y += as_[mt][nt][1] + bsv.y;
            s1.x += as_[mt][nt][2] + bsv.x; s1.y += as_[mt][nt][3] + bsv.y;
            *(float2*)&sacc[i0] = s0;
            *(float2*)&sacc[i1] = s1;
        }
    }
}

// ---- generic tf32 GEMM: C = act(A @ W^T + bias) ----
template <int KTOT, bool RELU, bool ROUND>
__global__ __launch_bounds__(256, 2) void k_gemm(
    const float* __restrict__ A, const float* __restrict__ W,
    const float* __restrict__ bias, float* __restrict__ C, int N) {
    extern __shared__ float sm[];
    const int STG = 128 * ASTR + 64 * ASTR;   // 6912 floats
    int tid = threadIdx.x;
    int lane = tid & 31, wid = tid >> 5;
    int wm = (wid & 3) * 32, wn = (wid >> 2) * 32;
    int m0 = blockIdx.y * 128, n0 = blockIdx.x * 64;

    float acc[2][4][4] = {};

    auto issue = [&](int chunk, int st) {
        int ci0 = chunk * KC;
        float* As = sm + st * STG;
        float* Wsm = As + 128 * ASTR;
#pragma unroll
        for (int j = 0; j < 4; j++) {
            int idx = tid + 256 * j;
            int row = idx >> 3, cg = idx & 7;
            unsigned sa = (unsigned)__cvta_generic_to_shared(As + row * ASTR + cg * 4);
            CP16(sa, A + (size_t)(m0 + row) * KTOT + ci0 + cg * 4);
        }
#pragma unroll
        for (int j = 0; j < 2; j++) {
            int idx = tid + 256 * j;
            int row = idx >> 3, cg = idx & 7;
            unsigned sw = (unsigned)__cvta_generic_to_shared(Wsm + row * ASTR + cg * 4);
            CP16(sw, W + (size_t)(n0 + row) * KTOT + ci0 + cg * 4);
        }
    };

    int r = lane >> 2, c = lane & 3;
    const int NCH = KTOT / KC;

    issue(0, 0);
    CP_COMMIT();
    for (int chunk = 0; chunk < NCH; chunk++) {
        int st = chunk & 1;
        if (chunk + 1 < NCH) {
            issue(chunk + 1, st ^ 1);
            CP_COMMIT();
            CP_WAIT1();
        } else {
            CP_WAIT0();
        }
        __syncthreads();
        const float* As = sm + st * STG;
        const float* Wsm = As + 128 * ASTR;
#pragma unroll
        for (int k8 = 0; k8 < 4; k8++) {
            int kb = k8 * 8;
            unsigned a[2][4];
#pragma unroll
            for (int mt = 0; mt < 2; mt++) {
                const float* ab = As + (wm + mt * 16 + r) * ASTR + kb + c;
                a[mt][0] = __float_as_uint(ab[0]);
                a[mt][1] = __float_as_uint(ab[8 * ASTR]);
                a[mt][2] = __float_as_uint(ab[4]);
                a[mt][3] = __float_as_uint(ab[8 * ASTR + 4]);
            }
#pragma unroll
            for (int nt = 0; nt < 4; nt++) {
                const float* wb = Wsm + (wn + nt * 8 + r) * ASTR + kb + c;
                unsigned b0 = __float_as_uint(wb[0]);
                unsigned b1 = __float_as_uint(wb[4]);
                MMA_TF32(acc[0][nt], a[0], b0, b1);
                MMA_TF32(acc[1][nt], a[1], b0, b1);
            }
        }
        __syncthreads();
    }

    int c2 = (lane & 3) * 2;
#pragma unroll
    for (int mt = 0; mt < 2; mt++) {
        int mrow = m0 + wm + mt * 16 + r;
#pragma unroll
        for (int nt = 0; nt < 4; nt++) {
            int col = n0 + wn + nt * 8 + c2;
            float2 bv = *(const float2*)&bias[col];
            float v0 = acc[mt][nt][0] + bv.x;
            float v1 = acc[mt][nt][1] + bv.y;
            float v2 = acc[mt][nt][2] + bv.x;
            float v3 = acc[mt][nt][3] + bv.y;
            if (RELU) {
                v0 = fmaxf(v0, 0.f); v1 = fmaxf(v1, 0.f);
                v2 = fmaxf(v2, 0.f); v3 = fmaxf(v3, 0.f);
            }
            if (ROUND) {
                v0 = rndf(v0); v1 = rndf(v1); v2 = rndf(v2); v3 = rndf(v3);
            }
            *(float2*)&C[(size_t)mrow * N + col] = make_float2(v0, v1);
            *(float2*)&C[(size_t)(mrow + 8) * N + col] = make_float2(v2, v3);
        }
    }
}

// ---------------- launch ----------------
extern "C" void kernel_launch(void* const* d_in, const int* in_sizes, int n_in,
                              void* d_out, int out_size) {
    const float* x           = (const float*)d_in[0];
    const float* W_in        = (const float*)d_in[1];
    const float* b_in        = (const float*)d_in[2];
    const float* W_f         = (const float*)d_in[3];
    const float* b_f         = (const float*)d_in[4];
    const float* W_g         = (const float*)d_in[5];
    const float* b_g         = (const float*)d_in[6];
    const float* W_r         = (const float*)d_in[7];
    const float* b_r         = (const float*)d_in[8];
    const float* W_s         = (const float*)d_in[9];
    const float* b_s         = (const float*)d_in[10];
    const float* norm_w      = (const float*)d_in[11];
    const float* head_norm_w = (const float*)d_in[12];
    const float* W1          = (const float*)d_in[13];
    const float* b1          = (const float*)d_in[14];
    const float* W2          = (const float*)d_in[15];
    const float* b2          = (const float*)d_in[16];
    float* out = (float*)d_out;

    float *zp, *znp, *up, *sump, *hp;
    float *wfp, *wgp, *wrp, *wsp, *w1p, *w2p;
    cudaGetSymbolAddress((void**)&zp, g_z);
    cudaGetSymbolAddress((void**)&znp, g_zn);
    cudaGetSymbolAddress((void**)&up, g_u);
    cudaGetSymbolAddress((void**)&sump, g_sum);
    cudaGetSymbolAddress((void**)&hp, g_h);
    cudaGetSymbolAddress((void**)&wfp, g_Wfp);
    cudaGetSymbolAddress((void**)&wgp, g_Wgp);
    cudaGetSymbolAddress((void**)&wrp, g_Wrp);
    cudaGetSymbolAddress((void**)&wsp, g_Wsp);
    cudaGetSymbolAddress((void**)&w1p, g_W1p);
    cudaGetSymbolAddress((void**)&w2p, g_W2p);

    // opt-in to large dynamic smem
    cudaFuncSetAttribute(k_fg, cudaFuncAttributeMaxDynamicSharedMemorySize, 73728);
    cudaFuncSetAttribute(k_rs, cudaFuncAttributeMaxDynamicSharedMemorySize, 73728);
    cudaFuncSetAttribute(k_gemm<CDIM, true, true>,
                         cudaFuncAttributeMaxDynamicSharedMemorySize, 55296);
    cudaFuncSetAttribute(k_gemm<HID, false, false>,
                         cudaFuncAttributeMaxDynamicSharedMemorySize, 55296);

    static const int DIL[NLAYER] = {1, 2, 4, 8, 16, 32, 64, 128, 256, 512,
                                    1, 2, 4, 8, 16, 32, 64, 128, 256, 512};

    // weight prep (tf32 rounding + fg tap de-interleave)
    k_prep_fg<<<NLAYER * 2 * CDIM * CDIM / 256, 256>>>(W_f, W_g, wfp, wgp);
    k_prep_round<<<NLAYER * CDIM * CDIM / 256, 256>>>(W_r, wrp, NLAYER * CDIM * CDIM);
    k_prep_round<<<NLAYER * CDIM * CDIM / 256, 256>>>(W_s, wsp, NLAYER * CDIM * CDIM);
    k_prep_round<<<HID * CDIM / 256, 256>>>(W1, w1p, HID * CDIM);
    k_prep_round<<<OUTC * HID / 256, 256>>>(W2, w2p, OUTC * HID);

    dim3 nrmB(32, 8);
    k_zero<<<BT * CDIM / 256, 256>>>(sump);
    k_inconv<<<dim3(CDIM / 64, BT / 64), 256>>>(x, W_in, b_in, zp);

    dim3 gFG(CDIM / 64, BT / 128);   // (4, 512)
    for (int i = 0; i < NLAYER; i++) {
        k_norm<false><<<BT / 8, nrmB>>>(zp, norm_w + i * CDIM, znp);
        k_fg<<<gFG, 256, 73728>>>(znp,
                                  wfp + (size_t)i * 2 * CDIM * CDIM,
                                  wgp + (size_t)i * 2 * CDIM * CDIM,
                                  b_f + i * CDIM, b_g + i * CDIM, up, DIL[i]);
        k_rs<<<gFG, 256, 73728>>>(up,
                                  wrp + (size_t)i * CDIM * CDIM,
                                  wsp + (size_t)i * CDIM * CDIM,
                                  b_r + i * CDIM, b_s + i * CDIM, zp, sump);
    }

    k_norm<true><<<BT / 8, nrmB>>>(sump, head_norm_w, znp);
    k_gemm<CDIM, true, true><<<dim3(HID / 64, BT / 128), 256, 55296>>>(znp, w1p, b1, hp, HID);
    k_gemm<HID, false, false><<<dim3(OUTC / 64, BT / 128), 256, 55296>>>(hp, w2p, b2, out, OUTC);
}